// round 2
// baseline (speedup 1.0000x reference)
#include <cuda_runtime.h>
#include <cuda_fp16.h>
#include <cstdint>

// ============================================================================
// GhostLinear: out[M,N] = X[M,K] @ W^T,  W[N,K] = lut[indices]*scale
// M=16384 (B*S), N=4096 (OUT), K=4096 (IN)
//
// Toolchain constraint (learned R1): harness PTX target is sm_103 (no 'a'),
// so tcgen05.ld/st/dealloc are unavailable -> TMEM results unreadable.
// Use base-ISA path: mma.sync.m16n8k16 fp16 (HMMA) + cp.async pipeline.
// ============================================================================

#define M_TOTAL 16384
#define N_TOTAL 4096
#define K_TOTAL 4096
#define CODES   256

#define BM 128
#define BN 256
#define BK 32
#define STAGES 5
#define NITER (K_TOTAL / BK)            // 128

#define BKP 40                           // padded halves per smem row (80 B)
#define A_STAGE_HALFS (BM * BKP)         // 5120
#define B_STAGE_HALFS (BN * BKP)         // 10240
#define STAGE_HALFS (A_STAGE_HALFS + B_STAGE_HALFS)
#define SMEM_BYTES (STAGES * STAGE_HALFS * 2)   // 153600

// fp16 scratch (allocation-free: __device__ globals)
__device__ __align__(1024) __half g_X[(size_t)M_TOTAL * K_TOTAL];  // 128 MB
__device__ __align__(1024) __half g_W[(size_t)N_TOTAL * K_TOTAL];  //  32 MB

__device__ __forceinline__ uint32_t smem_u32(const void* p) {
    uint32_t a;
    asm("{ .reg .u64 t; cvta.to.shared.u64 t, %1; cvt.u32.u64 %0, t; }"
        : "=r"(a) : "l"(p));
    return a;
}

#define CP_ASYNC16(dst32, src) \
    asm volatile("cp.async.cg.shared.global [%0], [%1], 16;" \
                 :: "r"(dst32), "l"(src) : "memory")
#define CP_COMMIT() asm volatile("cp.async.commit_group;" ::: "memory")
#define CP_WAIT(n)  asm volatile("cp.async.wait_group %0;" :: "n"(n) : "memory")

__device__ __forceinline__ void mma16816(float* c, const uint32_t* a, const uint32_t* b) {
    asm volatile(
        "mma.sync.aligned.m16n8k16.row.col.f32.f16.f16.f32 "
        "{%0,%1,%2,%3}, {%4,%5,%6,%7}, {%8,%9}, {%0,%1,%2,%3};"
        : "+f"(c[0]), "+f"(c[1]), "+f"(c[2]), "+f"(c[3])
        : "r"(a[0]), "r"(a[1]), "r"(a[2]), "r"(a[3]), "r"(b[0]), "r"(b[1]));
}

// ---------------------------------------------------------------------------
// Converters: fp32 -> fp16, and codebook dequant -> fp16
// ---------------------------------------------------------------------------
__device__ __forceinline__ uint32_t h2u(__half2 h) {
    return *reinterpret_cast<uint32_t*>(&h);
}

__global__ void __launch_bounds__(256) convert_x_kernel(const float* __restrict__ x,
                                                        __half* __restrict__ X) {
    size_t i = ((size_t)blockIdx.x * 256 + threadIdx.x) * 8;
    float4 a = *reinterpret_cast<const float4*>(x + i);
    float4 b = *reinterpret_cast<const float4*>(x + i + 4);
    uint4 o;
    o.x = h2u(__floats2half2_rn(a.x, a.y));
    o.y = h2u(__floats2half2_rn(a.z, a.w));
    o.z = h2u(__floats2half2_rn(b.x, b.y));
    o.w = h2u(__floats2half2_rn(b.z, b.w));
    *reinterpret_cast<uint4*>(X + i) = o;
}

__global__ void __launch_bounds__(256) dequant_w_kernel(const int* __restrict__ idx,
                                                        const float* __restrict__ scale,
                                                        const float* __restrict__ lut,
                                                        __half* __restrict__ W) {
    __shared__ float slut[CODES];
    if (threadIdx.x < CODES) slut[threadIdx.x] = lut[threadIdx.x];
    __syncthreads();
    size_t i = ((size_t)blockIdx.x * 256 + threadIdx.x) * 4;
    int4 v = *reinterpret_cast<const int4*>(idx + i);
    float s = scale[i >> 12];  // K_TOTAL = 4096 elements per output row
    uint2 o;
    o.x = h2u(__floats2half2_rn(slut[v.x] * s, slut[v.y] * s));
    o.y = h2u(__floats2half2_rn(slut[v.z] * s, slut[v.w] * s));
    *reinterpret_cast<uint2*>(W + i) = o;
}

// ---------------------------------------------------------------------------
// GEMM: CTA = 128(M) x 256(N) x K, BK=32 chunks, 5-stage cp.async pipeline.
// 512 threads = 16 warps in 4(M) x 4(N) grid; warp tile 32 x 64.
// mma.sync m16n8k16: warp tile = 2 m-tiles x 8 n-tiles.
// ---------------------------------------------------------------------------
__global__ void __launch_bounds__(512, 1) gemm_kernel(const __half* __restrict__ X,
                                                      const __half* __restrict__ W,
                                                      float* __restrict__ out) {
    extern __shared__ __half sm[];
    const uint32_t smem_base = smem_u32(sm);
    const int tid  = threadIdx.x;
    const int lane = tid & 31;
    const int wid  = tid >> 5;
    const int warp_m = wid & 3;    // 0..3 -> 32-row bands
    const int warp_n = wid >> 2;   // 0..3 -> 64-col bands
    const int m_base = blockIdx.y * BM;
    const int n_base = blockIdx.x * BN;

    // --- cp.async source/dest mapping (per thread: 1 A chunk + 2 B chunks) ---
    const int ar = tid >> 2, ac = tid & 3;                 // A: 128 rows x 4 chunks
    const int q0 = tid * 2, q1 = tid * 2 + 1;              // B: 256 rows x 4 chunks
    const int br0 = q0 >> 2, bc0 = q0 & 3;
    const int br1 = q1 >> 2, bc1 = q1 & 3;
    const __half* gA  = X + (size_t)(m_base + ar)  * K_TOTAL + ac  * 8;
    const __half* gB0 = W + (size_t)(n_base + br0) * K_TOTAL + bc0 * 8;
    const __half* gB1 = W + (size_t)(n_base + br1) * K_TOTAL + bc1 * 8;
    const uint32_t dA  = (uint32_t)(ar  * BKP + ac  * 8) * 2;
    const uint32_t dB0 = (uint32_t)(A_STAGE_HALFS + br0 * BKP + bc0 * 8) * 2;
    const uint32_t dB1 = (uint32_t)(A_STAGE_HALFS + br1 * BKP + bc1 * 8) * 2;

    float acc[2][8][4];
    #pragma unroll
    for (int t = 0; t < 2; t++)
        #pragma unroll
        for (int j = 0; j < 8; j++)
            #pragma unroll
            for (int e = 0; e < 4; e++) acc[t][j][e] = 0.f;

    // --- prologue: fill STAGES-1 stages ---
    #pragma unroll
    for (int s = 0; s < STAGES - 1; s++) {
        uint32_t sb = smem_base + (uint32_t)(s * STAGE_HALFS) * 2;
        int koff = s * BK;
        CP_ASYNC16(sb + dA,  gA  + koff);
        CP_ASYNC16(sb + dB0, gB0 + koff);
        CP_ASYNC16(sb + dB1, gB1 + koff);
        CP_COMMIT();
    }

    // --- main loop ---
    for (int kit = 0; kit < NITER; kit++) {
        CP_WAIT(STAGES - 2);
        __syncthreads();

        // issue prefetch for kit + STAGES-1
        {
            int pf = kit + STAGES - 1;
            if (pf < NITER) {
                int st = pf % STAGES;
                uint32_t sb = smem_base + (uint32_t)(st * STAGE_HALFS) * 2;
                int koff = pf * BK;
                CP_ASYNC16(sb + dA,  gA  + koff);
                CP_ASYNC16(sb + dB0, gB0 + koff);
                CP_ASYNC16(sb + dB1, gB1 + koff);
            }
            CP_COMMIT();
        }

        // compute on stage kit % STAGES
        const __half* hs = sm + (kit % STAGES) * STAGE_HALFS;
        const __half* sA = hs;
        const __half* sB = hs + A_STAGE_HALFS;

        #pragma unroll
        for (int ks = 0; ks < 2; ks++) {
            const int colk = ks * 16 + (lane & 3) * 2;
            uint32_t a[2][4], b[8][2];
            #pragma unroll
            for (int t = 0; t < 2; t++) {
                int r0 = warp_m * 32 + t * 16 + (lane >> 2);
                a[t][0] = *(const uint32_t*)(sA + r0 * BKP + colk);
                a[t][1] = *(const uint32_t*)(sA + (r0 + 8) * BKP + colk);
                a[t][2] = *(const uint32_t*)(sA + r0 * BKP + colk + 8);
                a[t][3] = *(const uint32_t*)(sA + (r0 + 8) * BKP + colk + 8);
            }
            #pragma unroll
            for (int j = 0; j < 8; j++) {
                int n0 = warp_n * 64 + j * 8 + (lane >> 2);
                b[j][0] = *(const uint32_t*)(sB + n0 * BKP + colk);
                b[j][1] = *(const uint32_t*)(sB + n0 * BKP + colk + 8);
            }
            #pragma unroll
            for (int t = 0; t < 2; t++)
                #pragma unroll
                for (int j = 0; j < 8; j++)
                    mma16816(acc[t][j], a[t], b[j]);
        }
    }

    // --- epilogue: direct f32 stores ---
    #pragma unroll
    for (int t = 0; t < 2; t++) {
        int row = m_base + warp_m * 32 + t * 16 + (lane >> 2);
        #pragma unroll
        for (int j = 0; j < 8; j++) {
            int col = n_base + warp_n * 64 + j * 8 + (lane & 3) * 2;
            float2 v0 = make_float2(acc[t][j][0], acc[t][j][1]);
            float2 v1 = make_float2(acc[t][j][2], acc[t][j][3]);
            *reinterpret_cast<float2*>(out + (size_t)row * N_TOTAL + col) = v0;
            *reinterpret_cast<float2*>(out + (size_t)(row + 8) * N_TOTAL + col) = v1;
        }
    }
}

// ---------------------------------------------------------------------------
// Host launcher
// ---------------------------------------------------------------------------
extern "C" void kernel_launch(void* const* d_in, const int* in_sizes, int n_in,
                              void* d_out, int out_size) {
    (void)in_sizes; (void)n_in; (void)out_size;
    const float* x     = (const float*)d_in[0];
    const float* scale = (const float*)d_in[1];
    const float* lut   = (const float*)d_in[2];
    const int*   idx   = (const int*)d_in[3];
    float* out = (float*)d_out;

    void *pX = nullptr, *pW = nullptr;
    cudaGetSymbolAddress(&pX, g_X);
    cudaGetSymbolAddress(&pW, g_W);

    cudaFuncSetAttribute(gemm_kernel, cudaFuncAttributeMaxDynamicSharedMemorySize,
                         SMEM_BYTES);

    // 67108864 elems / 8 per-thread / 256 threads = 32768 blocks
    convert_x_kernel<<<32768, 256>>>(x, (__half*)pX);
    // 16777216 / 4 / 256 = 16384 blocks
    dequant_w_kernel<<<16384, 256>>>(idx, scale, lut, (__half*)pW);

    dim3 grid(N_TOTAL / BN, M_TOTAL / BM);  // (16, 128): x fastest -> A-band reuse in L2
    gemm_kernel<<<grid, 512, SMEM_BYTES>>>((const __half*)pX, (const __half*)pW, out);
}

// round 3
// speedup vs baseline: 1.1276x; 1.1276x over previous
#include <cuda_runtime.h>
#include <cuda_fp16.h>
#include <cstdint>

// ============================================================================
// GhostLinear: out[M,N] = X[M,K] @ W^T,  W[N,K] = lut[indices]*scale
// M=16384, N=4096, K=4096
// Toolchain: PTX target is sm_103 (no 'a') -> tcgen05.ld unavailable -> TMEM
// unreadable -> legacy mma.sync path. Measured legacy HMMA ceiling ~512
// MAC/cyc/SM => GEMM floor ~1.93ms. This round: shave barrier/issue slack,
// fuse converters, land the GEMM in the ncu capture slot.
// ============================================================================

#define M_TOTAL 16384
#define N_TOTAL 4096
#define K_TOTAL 4096
#define CODES   256

#define BM 128
#define BN 256
#define BK 64
#define STAGES 4
#define NITER (K_TOTAL / BK)             // 64

#define BKP 72                            // padded halves per smem row (144 B)
#define A_STAGE_HALFS (BM * BKP)          // 9216
#define B_STAGE_HALFS (BN * BKP)          // 18432
#define STAGE_HALFS (A_STAGE_HALFS + B_STAGE_HALFS)      // 27648
#define SMEM_BYTES (STAGES * STAGE_HALFS * 2)            // 221184

__device__ __align__(1024) __half g_X[(size_t)M_TOTAL * K_TOTAL];  // 128 MB
__device__ __align__(1024) __half g_W[(size_t)N_TOTAL * K_TOTAL];  //  32 MB

__device__ __forceinline__ uint32_t smem_u32(const void* p) {
    uint32_t a;
    asm("{ .reg .u64 t; cvta.to.shared.u64 t, %1; cvt.u32.u64 %0, t; }"
        : "=r"(a) : "l"(p));
    return a;
}

#define CP_ASYNC16(dst32, src) \
    asm volatile("cp.async.cg.shared.global [%0], [%1], 16;" \
                 :: "r"(dst32), "l"(src) : "memory")
#define CP_COMMIT() asm volatile("cp.async.commit_group;" ::: "memory")
#define CP_WAIT(n)  asm volatile("cp.async.wait_group %0;" :: "n"(n) : "memory")

#define LDSM4(r0, r1, r2, r3, addr) \
    asm volatile("ldmatrix.sync.aligned.m8n8.x4.shared.b16 {%0,%1,%2,%3}, [%4];" \
                 : "=r"(r0), "=r"(r1), "=r"(r2), "=r"(r3) : "r"(addr))

__device__ __forceinline__ void mma16816(float* c, const uint32_t* a, const uint32_t* b) {
    asm volatile(
        "mma.sync.aligned.m16n8k16.row.col.f32.f16.f16.f32 "
        "{%0,%1,%2,%3}, {%4,%5,%6,%7}, {%8,%9}, {%0,%1,%2,%3};"
        : "+f"(c[0]), "+f"(c[1]), "+f"(c[2]), "+f"(c[3])
        : "r"(a[0]), "r"(a[1]), "r"(a[2]), "r"(a[3]), "r"(b[0]), "r"(b[1]));
}

// ---------------------------------------------------------------------------
// Fused converter: blocks [0, XB) convert X fp32->fp16 (8/thread),
// blocks [XB, XB+WB) dequant W via codebook (4/thread).
// ---------------------------------------------------------------------------
#define XBLOCKS 32768
#define WBLOCKS 16384

__device__ __forceinline__ uint32_t h2u(__half2 h) {
    return *reinterpret_cast<uint32_t*>(&h);
}

__global__ void __launch_bounds__(256) convert_kernel(const float* __restrict__ x,
                                                      const int* __restrict__ idx,
                                                      const float* __restrict__ scale,
                                                      const float* __restrict__ lut) {
    if (blockIdx.x < XBLOCKS) {
        size_t i = ((size_t)blockIdx.x * 256 + threadIdx.x) * 8;
        float4 a = *reinterpret_cast<const float4*>(x + i);
        float4 b = *reinterpret_cast<const float4*>(x + i + 4);
        uint4 o;
        o.x = h2u(__floats2half2_rn(a.x, a.y));
        o.y = h2u(__floats2half2_rn(a.z, a.w));
        o.z = h2u(__floats2half2_rn(b.x, b.y));
        o.w = h2u(__floats2half2_rn(b.z, b.w));
        *reinterpret_cast<uint4*>(g_X + i) = o;
    } else {
        __shared__ float slut[CODES];
        if (threadIdx.x < CODES) slut[threadIdx.x] = lut[threadIdx.x];
        __syncthreads();
        size_t i = ((size_t)(blockIdx.x - XBLOCKS) * 256 + threadIdx.x) * 4;
        int4 v = *reinterpret_cast<const int4*>(idx + i);
        float s = scale[i >> 12];   // K_TOTAL elements per output row
        uint2 o;
        o.x = h2u(__floats2half2_rn(slut[v.x] * s, slut[v.y] * s));
        o.y = h2u(__floats2half2_rn(slut[v.z] * s, slut[v.w] * s));
        *reinterpret_cast<uint2*>(g_W + i) = o;
    }
}

// ---------------------------------------------------------------------------
// GEMM: CTA = 128(M) x 256(N), BK=64, 4-stage cp.async pipeline.
// 512 threads = 16 warps in 4(M) x 4(N); warp tile 32 x 64.
// Fragments via ldmatrix.x4 (conflict-free: row stride 144B = 36 banks).
// ---------------------------------------------------------------------------
__global__ void __launch_bounds__(512, 1) gemm_kernel(const __half* __restrict__ X,
                                                      const __half* __restrict__ W,
                                                      float* __restrict__ out) {
    extern __shared__ __half sm[];
    const uint32_t smem_base = smem_u32(sm);
    const int tid  = threadIdx.x;
    const int lane = tid & 31;
    const int wid  = tid >> 5;
    const int warp_m = wid & 3;    // 32-row band
    const int warp_n = wid >> 2;   // 64-col band
    const int m_base = blockIdx.y * BM;
    const int n_base = blockIdx.x * BN;

    // --- cp.async mapping: per thread 2 A chunks + 4 B chunks of 16B ---
    // A: 128 rows x 8 chunks = 1024; B: 256 rows x 8 chunks = 2048.
    const int a0i = tid * 2, a1i = tid * 2 + 1;
    const int ar0 = a0i >> 3, ac0 = a0i & 7;
    const int ar1 = a1i >> 3, ac1 = a1i & 7;
    const __half* gA0 = X + (size_t)(m_base + ar0) * K_TOTAL + ac0 * 8;
    const __half* gA1 = X + (size_t)(m_base + ar1) * K_TOTAL + ac1 * 8;
    const uint32_t dA0 = (uint32_t)(ar0 * BKP + ac0 * 8) * 2;
    const uint32_t dA1 = (uint32_t)(ar1 * BKP + ac1 * 8) * 2;
    const __half* gB[4];
    uint32_t dB[4];
    #pragma unroll
    for (int q = 0; q < 4; q++) {
        int bi = tid * 4 + q;
        int br = bi >> 3, bc = bi & 7;
        gB[q] = W + (size_t)(n_base + br) * K_TOTAL + bc * 8;
        dB[q] = (uint32_t)(A_STAGE_HALFS + br * BKP + bc * 8) * 2;
    }

    // --- ldmatrix per-thread address components ---
    // A tile t: row = warp_m*32 + t*16 + (lane&15), koff = ks*16 + (lane>>4)*8
    const int a_row_in  = warp_m * 32 + (lane & 15);
    const int a_koff_in = (lane >> 4) * 8;
    // B pair jj: n = warp_n*64 + jj*16 + (lane&7) + ((lane>>4)&1)*8,
    //            koff = ks*16 + ((lane>>3)&1)*8
    const int b_n_in    = warp_n * 64 + (lane & 7) + ((lane >> 4) & 1) * 8;
    const int b_koff_in = ((lane >> 3) & 1) * 8;

    float acc[2][8][4];
    #pragma unroll
    for (int t = 0; t < 2; t++)
        #pragma unroll
        for (int j = 0; j < 8; j++)
            #pragma unroll
            for (int e = 0; e < 4; e++) acc[t][j][e] = 0.f;

    // --- prologue: fill STAGES-1 stages ---
    #pragma unroll
    for (int s = 0; s < STAGES - 1; s++) {
        uint32_t sb = smem_base + (uint32_t)(s * STAGE_HALFS) * 2;
        int koff = s * BK;
        CP_ASYNC16(sb + dA0, gA0 + koff);
        CP_ASYNC16(sb + dA1, gA1 + koff);
        #pragma unroll
        for (int q = 0; q < 4; q++) CP_ASYNC16(sb + dB[q], gB[q] + koff);
        CP_COMMIT();
    }

    // --- main loop ---
    for (int kit = 0; kit < NITER; kit++) {
        CP_WAIT(STAGES - 2);
        __syncthreads();

        {   // prefetch stage kit + STAGES-1
            int pf = kit + STAGES - 1;
            if (pf < NITER) {
                uint32_t sb = smem_base + (uint32_t)((pf % STAGES) * STAGE_HALFS) * 2;
                int koff = pf * BK;
                CP_ASYNC16(sb + dA0, gA0 + koff);
                CP_ASYNC16(sb + dA1, gA1 + koff);
                #pragma unroll
                for (int q = 0; q < 4; q++) CP_ASYNC16(sb + dB[q], gB[q] + koff);
            }
            CP_COMMIT();
        }

        const uint32_t sb = smem_base + (uint32_t)((kit % STAGES) * STAGE_HALFS) * 2;
        const uint32_t sA = sb;
        const uint32_t sB = sb + A_STAGE_HALFS * 2;

        #pragma unroll
        for (int ks = 0; ks < 4; ks++) {        // four k16 steps in BK=64
            const int colk = ks * 16;
            uint32_t a[2][4], b[8][2];
            #pragma unroll
            for (int t = 0; t < 2; t++) {
                uint32_t addr = sA + (uint32_t)((a_row_in + t * 16) * BKP
                                              + colk + a_koff_in) * 2;
                LDSM4(a[t][0], a[t][1], a[t][2], a[t][3], addr);
            }
            #pragma unroll
            for (int jj = 0; jj < 4; jj++) {    // each x4 covers 2 n-tiles
                uint32_t addr = sB + (uint32_t)((b_n_in + jj * 16) * BKP
                                              + colk + b_koff_in) * 2;
                LDSM4(b[jj * 2][0], b[jj * 2][1], b[jj * 2 + 1][0], b[jj * 2 + 1][1], addr);
            }
            #pragma unroll
            for (int t = 0; t < 2; t++)
                #pragma unroll
                for (int j = 0; j < 8; j++)
                    mma16816(acc[t][j], a[t], b[j]);
        }
    }

    // --- epilogue ---
    #pragma unroll
    for (int t = 0; t < 2; t++) {
        int row = m_base + warp_m * 32 + t * 16 + (lane >> 2);
        #pragma unroll
        for (int j = 0; j < 8; j++) {
            int col = n_base + warp_n * 64 + j * 8 + (lane & 3) * 2;
            *reinterpret_cast<float2*>(out + (size_t)row * N_TOTAL + col) =
                make_float2(acc[t][j][0], acc[t][j][1]);
            *reinterpret_cast<float2*>(out + (size_t)(row + 8) * N_TOTAL + col) =
                make_float2(acc[t][j][2], acc[t][j][3]);
        }
    }
}

// ---------------------------------------------------------------------------
// Host launcher
// ---------------------------------------------------------------------------
extern "C" void kernel_launch(void* const* d_in, const int* in_sizes, int n_in,
                              void* d_out, int out_size) {
    (void)in_sizes; (void)n_in; (void)out_size;
    const float* x     = (const float*)d_in[0];
    const float* scale = (const float*)d_in[1];
    const float* lut   = (const float*)d_in[2];
    const int*   idx   = (const int*)d_in[3];
    float* out = (float*)d_out;

    void *pX = nullptr, *pW = nullptr;
    cudaGetSymbolAddress(&pX, g_X);
    cudaGetSymbolAddress(&pW, g_W);

    cudaFuncSetAttribute(gemm_kernel, cudaFuncAttributeMaxDynamicSharedMemorySize,
                         SMEM_BYTES);

    convert_kernel<<<XBLOCKS + WBLOCKS, 256>>>(x, idx, scale, lut);

    dim3 grid(N_TOTAL / BN, M_TOTAL / BM);   // (16, 128)
    gemm_kernel<<<grid, 512, SMEM_BYTES>>>((const __half*)pX, (const __half*)pW, out);
}